// round 9
// baseline (speedup 1.0000x reference)
#include <cuda_runtime.h>
#include <cuda_fp16.h>
#include <math.h>
#include <stdint.h>

#define BB 2
#define SS 2048
#define EE 256
#define HH 32

// log2(e)/sqrt(8): folded into the Q fragment (and the mask bias).
#define CSCALE 0.51006972790221780093f

__device__ uint32_t g_attnh[BB * SS * EE / 2];  // attention output, fp16x2 [B,S,E]
__device__ uint4 g_qh[64 * 2048];               // fp16 cos(x+theta): 8 vals (16B) per (bh,s)

// Warp-level fp16 MMA, D/C fp32. Baseline sm_80 PTX -> compiles for compute_103.
__device__ __forceinline__ void mma16816(float d[4],
    uint32_t a0, uint32_t a1, uint32_t a2, uint32_t a3,
    uint32_t b0, uint32_t b1, const float c[4])
{
    asm volatile("mma.sync.aligned.m16n8k16.row.col.f32.f16.f16.f32 "
        "{%0,%1,%2,%3}, {%4,%5,%6,%7}, {%8,%9}, {%10,%11,%12,%13};"
        : "=f"(d[0]), "=f"(d[1]), "=f"(d[2]), "=f"(d[3])
        : "r"(a0), "r"(a1), "r"(a2), "r"(a3), "r"(b0), "r"(b1),
          "f"(c[0]), "f"(c[1]), "f"(c[2]), "f"(c[3]));
}

// ---------------------------------------------------------------------------
// Prep: q = cos(x + theta) -> fp16. Thread = (token, head, half): 4 dims,
// one float4 load, one uint2 store. Fully coalesced, 2x parallelism of R8.
// ---------------------------------------------------------------------------
__global__ void prep_kernel(const float* __restrict__ x,
                            const float* __restrict__ theta)
{
    const int gid = blockIdx.x * 256 + threadIdx.x;   // over 2*2048*32*2
    const int hf  = gid & 1;                          // dim half
    const int h   = (gid >> 1) & 31;
    const int s   = (gid >> 6) & 2047;
    const int b   = gid >> 17;
    const float* xr = x + ((size_t)b * SS + s) * EE + h * 8 + hf * 4;
    float4 v = *reinterpret_cast<const float4*>(xr);
    float t0 = __ldg(theta + hf * 4 + 0);
    float t1 = __ldg(theta + hf * 4 + 1);
    float t2 = __ldg(theta + hf * 4 + 2);
    float t3 = __ldg(theta + hf * 4 + 3);
    half2 h0 = __floats2half2_rn(__cosf(v.x + t0), __cosf(v.y + t1));
    half2 h1 = __floats2half2_rn(__cosf(v.z + t2), __cosf(v.w + t3));
    uint2 pk = make_uint2(*reinterpret_cast<uint32_t*>(&h0),
                          *reinterpret_cast<uint32_t*>(&h1));
    uint32_t* dst = reinterpret_cast<uint32_t*>(g_qh + (((b << 5) + h) << 11) + s);
    *reinterpret_cast<uint2*>(dst + hf * 2) = pk;
}

// ---------------------------------------------------------------------------
// Warp-MMA flash attention, fp16 operands, double-buffered tiles.
// CTA = (bh, 128-query tile). Q pre-scaled by CSCALE; bias pre-scaled (-51).
// S -> fp16x2 -> ex2.approx.f16x2 (2 exps per MUFU op) -> P fragment direct.
// ---------------------------------------------------------------------------
__global__ __launch_bounds__(256, 3) void attn_kernel(const int* __restrict__ mask)
{
    __shared__ uint4    sK[2][128];      // K tile, 16B (8 fp16) per key
    __shared__ uint32_t sBias[2][128];   // {fp16 bias lo, 0 hi} per key
    __shared__ uint32_t sVT[2][8][68];   // V^T [dim][key-pair fp16x2], padded

    const int tid  = threadIdx.x;
    const int wid  = tid >> 5;
    const int lane = tid & 31;
    const int r = lane >> 2;             // fragment row group
    const int m = lane & 3;              // fragment k group
    const int bh = blockIdx.x >> 4;
    const int qt = blockIdx.x & 15;
    const int b  = bh >> 5;

    // --- Fixed A fragment: this warp's 16 queries, pre-scaled by CSCALE ---
    const int qbase = (bh << 11) + (qt << 7) + wid * 16;
    const uint32_t* qw = reinterpret_cast<const uint32_t*>(g_qh + qbase);
    uint32_t a0r = qw[r * 4 + m];                // row r,   dims 2m,2m+1
    uint32_t a1r = qw[(r + 8) * 4 + m];          // row r+8
    float2 f0 = __half22float2(*reinterpret_cast<half2*>(&a0r));
    float2 f1 = __half22float2(*reinterpret_cast<half2*>(&a1r));
    half2 s0 = __floats2half2_rn(f0.x * CSCALE, f0.y * CSCALE);
    half2 s1 = __floats2half2_rn(f1.x * CSCALE, f1.y * CSCALE);
    const uint32_t a0 = *reinterpret_cast<uint32_t*>(&s0);
    const uint32_t a1 = *reinterpret_cast<uint32_t*>(&s1);
    const uint32_t a2 = (m == 0) ? 0x3C00u : 0u; // col8 = 1.0 -> picks bias row
    const uint32_t a3 = a2;

    float O[4] = {0.f, 0.f, 0.f, 0.f};   // output fragment [16q x 8d]
    float l_lo = 0.f, l_hi = 0.f;        // softmax denominators (rows r, r+8)

    // --- Tile loader (buf selects double buffer) ---
    auto load_chunk = [&](int c, int buf) {
        const int kg = (bh << 11) + (c << 7);
        if (tid < 128) {
            sK[buf][tid] = g_qh[kg + tid];
            int mk = mask[b * SS + (c << 7) + tid];
            sBias[buf][tid] = mk ? 0u : 0xD260u;   // fp16(-51) = -100*CSCALE
        } else {
            int u  = (tid - 128) >> 1;             // key pair
            int hf = tid & 1;                      // dim half (4 dims)
            const uint32_t* ka = reinterpret_cast<const uint32_t*>(g_qh + kg + 2 * u);
            const uint32_t* kb = ka + 4;
            uint32_t ua0 = ka[hf * 2], ua1 = ka[hf * 2 + 1];
            uint32_t ub0 = kb[hf * 2], ub1 = kb[hf * 2 + 1];
            sVT[buf][hf * 4 + 0][u] = __byte_perm(ua0, ub0, 0x5410);
            sVT[buf][hf * 4 + 1][u] = __byte_perm(ua0, ub0, 0x7632);
            sVT[buf][hf * 4 + 2][u] = __byte_perm(ua1, ub1, 0x5410);
            sVT[buf][hf * 4 + 3][u] = __byte_perm(ua1, ub1, 0x7632);
        }
    };

    load_chunk(0, 0);
    __syncthreads();

    for (int c = 0; c < 16; c++) {
        const int buf = c & 1;
        if (c < 15) load_chunk(c + 1, buf ^ 1);

        const uint32_t* k32 = reinterpret_cast<const uint32_t*>(sK[buf]);

        // --- S = (Q*CSCALE)K^T + bias; fp16 round; exp2 two-at-a-time ---
        uint32_t P[16][2];
#pragma unroll
        for (int j = 0; j < 16; j++) {
            int key = 8 * j + r;
            uint32_t b0 = k32[key * 4 + m];            // K dims 2m,2m+1
            uint32_t b1 = (m == 0) ? sBias[buf][key] : 0u;
            float D[4] = {0.f, 0.f, 0.f, 0.f};
            mma16816(D, a0, a1, a2, a3, b0, b1, D);
            uint32_t sA, sB, pA, pB;
            asm("cvt.rn.f16x2.f32 %0, %1, %2;" : "=r"(sA) : "f"(D[1]), "f"(D[0]));
            asm("cvt.rn.f16x2.f32 %0, %1, %2;" : "=r"(sB) : "f"(D[3]), "f"(D[2]));
            asm("ex2.approx.f16x2 %0, %1;" : "=r"(pA) : "r"(sA));
            asm("ex2.approx.f16x2 %0, %1;" : "=r"(pB) : "r"(sB));
            P[j][0] = pA;
            P[j][1] = pB;
            // denominator: exact unpack of the SAME rounded P (consistency)
            float2 fa = __half22float2(*reinterpret_cast<half2*>(&pA));
            float2 fb = __half22float2(*reinterpret_cast<half2*>(&pB));
            l_lo += fa.x + fa.y;
            l_hi += fb.x + fb.y;
        }

        // --- O += P * V  (8 k16 steps over 128 keys) ---
#pragma unroll
        for (int t = 0; t < 8; t++) {
            uint32_t b0 = sVT[buf][r][t * 8 + m];
            uint32_t b1 = sVT[buf][r][t * 8 + 4 + m];
            mma16816(O, P[2 * t][0], P[2 * t][1], P[2 * t + 1][0], P[2 * t + 1][1],
                     b0, b1, O);
        }
        __syncthreads();
    }

    // --- Reduce denominators across the 4 threads sharing each row ---
    l_lo += __shfl_xor_sync(0xffffffffu, l_lo, 1);
    l_lo += __shfl_xor_sync(0xffffffffu, l_lo, 2);
    l_hi += __shfl_xor_sync(0xffffffffu, l_hi, 1);
    l_hi += __shfl_xor_sync(0xffffffffu, l_hi, 2);
    float inv_lo = 1.0f / l_lo;
    float inv_hi = 1.0f / l_hi;

    const int h  = bh & 31;
    const int q0 = (qt << 7) + wid * 16 + r;
    uint32_t* op = g_attnh + ((size_t)b * SS + q0) * 128 + h * 4 + m;
    half2 o1 = __floats2half2_rn(O[0] * inv_lo, O[1] * inv_lo);
    half2 o2 = __floats2half2_rn(O[2] * inv_hi, O[3] * inv_hi);
    op[0]       = *reinterpret_cast<uint32_t*>(&o1);
    op[8 * 128] = *reinterpret_cast<uint32_t*>(&o2);
}

// ---------------------------------------------------------------------------
// Output projection via fp16 MMA: Y[4096,256] = A @ W^T + b.
// CTA: 64x64 tile, full K=256 staged once (A fp16 + W cvt to fp16).
// ---------------------------------------------------------------------------
__global__ __launch_bounds__(256, 2) void proj_kernel(
    const float* __restrict__ W,
    const float* __restrict__ bo,
    float*       __restrict__ Y)
{
    extern __shared__ uint32_t sh[];     // As: 64*132 u32, Ws: 64*132 u32
    uint32_t* As = sh;
    uint32_t* Ws = sh + 64 * 132;

    const int tid = threadIdx.x;
    const int im0 = blockIdx.x * 64;
    const int jn0 = blockIdx.y * 64;

    // Stage A (already fp16): 64 rows x 128 u32, uint4 loads
#pragma unroll
    for (int l = 0; l < 8; l++) {
        int idx = l * 256 + tid;
        int row = idx >> 5, c4 = idx & 31;
        uint4 v = *reinterpret_cast<const uint4*>(
            g_attnh + (size_t)(im0 + row) * 128 + c4 * 4);
        *reinterpret_cast<uint4*>(As + row * 132 + c4 * 4) = v;
    }
    // Stage W with fp32->fp16 conversion: 64 rows x 64 float4
#pragma unroll
    for (int l = 0; l < 16; l++) {
        int idx = l * 256 + tid;
        int row = idx >> 6, c4 = idx & 63;
        float4 v = *reinterpret_cast<const float4*>(
            W + (size_t)(jn0 + row) * 256 + c4 * 4);
        half2 h0 = __floats2half2_rn(v.x, v.y);
        half2 h1 = __floats2half2_rn(v.z, v.w);
        uint2 pk = make_uint2(*reinterpret_cast<uint32_t*>(&h0),
                              *reinterpret_cast<uint32_t*>(&h1));
        *reinterpret_cast<uint2*>(Ws + row * 132 + c4 * 2) = pk;
    }
    __syncthreads();

    const int lane = tid & 31, wid = tid >> 5;
    const int r = lane >> 2, m = lane & 3;
    const int mb  = (wid & 3) * 16;      // m-block
    const int nb0 = (wid >> 2) * 32;     // 4 n8-blocks

    float acc[4][4];
#pragma unroll
    for (int nn = 0; nn < 4; nn++)
#pragma unroll
        for (int i = 0; i < 4; i++) acc[nn][i] = 0.f;

#pragma unroll
    for (int kc = 0; kc < 16; kc++) {
        uint32_t a0 = As[(mb + r) * 132 + kc * 8 + m];
        uint32_t a1 = As[(mb + r + 8) * 132 + kc * 8 + m];
        uint32_t a2 = As[(mb + r) * 132 + kc * 8 + 4 + m];
        uint32_t a3 = As[(mb + r + 8) * 132 + kc * 8 + 4 + m];
#pragma unroll
        for (int nn = 0; nn < 4; nn++) {
            uint32_t b0 = Ws[(nb0 + nn * 8 + r) * 132 + kc * 8 + m];
            uint32_t b1 = Ws[(nb0 + nn * 8 + r) * 132 + kc * 8 + 4 + m];
            mma16816(acc[nn], a0, a1, a2, a3, b0, b1, acc[nn]);
        }
    }

    // Epilogue: bias + fp32 stores
#pragma unroll
    for (int nn = 0; nn < 4; nn++) {
        int j = jn0 + nb0 + nn * 8 + 2 * m;
        float2 bv = *reinterpret_cast<const float2*>(bo + j);
        int i0 = im0 + mb + r;
        *reinterpret_cast<float2*>(Y + (size_t)i0 * 256 + j) =
            make_float2(acc[nn][0] + bv.x, acc[nn][1] + bv.y);
        *reinterpret_cast<float2*>(Y + (size_t)(i0 + 8) * 256 + j) =
            make_float2(acc[nn][2] + bv.x, acc[nn][3] + bv.y);
    }
}

// ---------------------------------------------------------------------------
extern "C" void kernel_launch(void* const* d_in, const int* in_sizes, int n_in,
                              void* d_out, int out_size)
{
    const float* x     = (const float*)d_in[0];
    const int*   mask  = (const int*)d_in[1];
    const float* theta = (const float*)d_in[2];
    const float* W     = (const float*)d_in[3];
    const float* bo    = (const float*)d_in[4];
    float*       out   = (float*)d_out;

    prep_kernel<<<BB * SS * HH * 2 / 256, 256>>>(x, theta);
    attn_kernel<<<64 * 16, 256>>>(mask);

    const int proj_smem = 2 * 64 * 132 * 4;   // 67.6 KB
    cudaFuncSetAttribute(proj_kernel,
                         cudaFuncAttributeMaxDynamicSharedMemorySize, proj_smem);
    dim3 grid(BB * SS / 64, EE / 64);  // (64, 4)
    proj_kernel<<<grid, 256, proj_smem>>>(W, bo, out);
}

// round 10
// speedup vs baseline: 1.0032x; 1.0032x over previous
#include <cuda_runtime.h>
#include <cuda_fp16.h>
#include <math.h>
#include <stdint.h>

#define BB 2
#define SS 2048
#define EE 256
#define HH 32

// log2(e)/sqrt(8): folded into the Q fragment.
#define CSCALE 0.51006972790221780093f

__device__ uint32_t g_attnh[BB * SS * EE / 2];  // attention output, fp16x2 [B,S,E]
__device__ uint4 g_qh[64 * 2048];               // fp16 cos(x+theta): 8 vals (16B) per (bh,s)

// Warp-level fp16 MMA m16n8k16, D/C fp32. Baseline sm_80 PTX.
__device__ __forceinline__ void mma16816(float d[4],
    uint32_t a0, uint32_t a1, uint32_t a2, uint32_t a3,
    uint32_t b0, uint32_t b1, const float c[4])
{
    asm volatile("mma.sync.aligned.m16n8k16.row.col.f32.f16.f16.f32 "
        "{%0,%1,%2,%3}, {%4,%5,%6,%7}, {%8,%9}, {%10,%11,%12,%13};"
        : "=f"(d[0]), "=f"(d[1]), "=f"(d[2]), "=f"(d[3])
        : "r"(a0), "r"(a1), "r"(a2), "r"(a3), "r"(b0), "r"(b1),
          "f"(c[0]), "f"(c[1]), "f"(c[2]), "f"(c[3]));
}
// Warp-level fp16 MMA m16n8k8 (half the FLOPs): exactly fits d_k=8.
__device__ __forceinline__ void mma16808(float d[4],
    uint32_t a0, uint32_t a1, uint32_t b0, const float c[4])
{
    asm volatile("mma.sync.aligned.m16n8k8.row.col.f32.f16.f16.f32 "
        "{%0,%1,%2,%3}, {%4,%5}, {%6}, {%7,%8,%9,%10};"
        : "=f"(d[0]), "=f"(d[1]), "=f"(d[2]), "=f"(d[3])
        : "r"(a0), "r"(a1), "r"(b0),
          "f"(c[0]), "f"(c[1]), "f"(c[2]), "f"(c[3]));
}

// ---------------------------------------------------------------------------
// Prep: q = cos(x + theta) -> fp16. Thread = (s, h) for BOTH batches (MLP=4).
// ---------------------------------------------------------------------------
__global__ void prep_kernel(const float* __restrict__ x,
                            const float* __restrict__ theta)
{
    const int gid = blockIdx.x * 256 + threadIdx.x;   // 0..65535
    const int h = gid & 31;
    const int s = (gid >> 5) & 2047;
    const float* xr0 = x + (size_t)s * EE + h * 8;           // b = 0
    const float* xr1 = xr0 + (size_t)SS * EE;                // b = 1
    float4 va0 = *reinterpret_cast<const float4*>(xr0);
    float4 va1 = *reinterpret_cast<const float4*>(xr0 + 4);
    float4 vb0 = *reinterpret_cast<const float4*>(xr1);
    float4 vb1 = *reinterpret_cast<const float4*>(xr1 + 4);
    float t[8];
#pragma unroll
    for (int d = 0; d < 8; d++) t[d] = __ldg(theta + d);

    half2 a0 = __floats2half2_rn(__cosf(va0.x + t[0]), __cosf(va0.y + t[1]));
    half2 a1 = __floats2half2_rn(__cosf(va0.z + t[2]), __cosf(va0.w + t[3]));
    half2 a2 = __floats2half2_rn(__cosf(va1.x + t[4]), __cosf(va1.y + t[5]));
    half2 a3 = __floats2half2_rn(__cosf(va1.z + t[6]), __cosf(va1.w + t[7]));
    half2 b0 = __floats2half2_rn(__cosf(vb0.x + t[0]), __cosf(vb0.y + t[1]));
    half2 b1 = __floats2half2_rn(__cosf(vb0.z + t[2]), __cosf(vb0.w + t[3]));
    half2 b2 = __floats2half2_rn(__cosf(vb1.x + t[4]), __cosf(vb1.y + t[5]));
    half2 b3 = __floats2half2_rn(__cosf(vb1.z + t[6]), __cosf(vb1.w + t[7]));

    uint4 HA = make_uint4(*reinterpret_cast<uint32_t*>(&a0),
                          *reinterpret_cast<uint32_t*>(&a1),
                          *reinterpret_cast<uint32_t*>(&a2),
                          *reinterpret_cast<uint32_t*>(&a3));
    uint4 HB = make_uint4(*reinterpret_cast<uint32_t*>(&b0),
                          *reinterpret_cast<uint32_t*>(&b1),
                          *reinterpret_cast<uint32_t*>(&b2),
                          *reinterpret_cast<uint32_t*>(&b3));
    g_qh[(h << 11) + s]          = HA;
    g_qh[((32 + h) << 11) + s]   = HB;
}

// ---------------------------------------------------------------------------
// Warp-MMA flash attention. S via m16n8k8 (K=8 exactly); mask applied by
// AND-ing packed fp16 P with per-key-pair mask words (exact masking).
// ---------------------------------------------------------------------------
__global__ __launch_bounds__(256, 3) void attn_kernel(const int* __restrict__ mask)
{
    __shared__ uint4    sK[2][128];      // K tile, 16B (8 fp16) per key
    __shared__ uint32_t sMaskP[2][64];   // {m(2u) ? 0xFFFF, m(2u+1) ? 0xFFFF0000}
    __shared__ uint32_t sVT[2][8][68];   // V^T [dim][key-pair fp16x2], padded

    const int tid  = threadIdx.x;
    const int wid  = tid >> 5;
    const int lane = tid & 31;
    const int r = lane >> 2;             // fragment row group
    const int m = lane & 3;              // fragment k group
    const int bh = blockIdx.x >> 4;
    const int qt = blockIdx.x & 15;
    const int b  = bh >> 5;

    // --- Fixed A fragment: this warp's 16 queries, pre-scaled by CSCALE ---
    const int qbase = (bh << 11) + (qt << 7) + wid * 16;
    const uint32_t* qw = reinterpret_cast<const uint32_t*>(g_qh + qbase);
    uint32_t a0r = qw[r * 4 + m];                // row r,   dims 2m,2m+1
    uint32_t a1r = qw[(r + 8) * 4 + m];          // row r+8
    float2 f0 = __half22float2(*reinterpret_cast<half2*>(&a0r));
    float2 f1 = __half22float2(*reinterpret_cast<half2*>(&a1r));
    half2 s0 = __floats2half2_rn(f0.x * CSCALE, f0.y * CSCALE);
    half2 s1 = __floats2half2_rn(f1.x * CSCALE, f1.y * CSCALE);
    const uint32_t a0 = *reinterpret_cast<uint32_t*>(&s0);
    const uint32_t a1 = *reinterpret_cast<uint32_t*>(&s1);

    float O[4] = {0.f, 0.f, 0.f, 0.f};   // output fragment [16q x 8d]
    float l_lo = 0.f, l_hi = 0.f;        // softmax denominators (rows r, r+8)

    // --- Tile loader (buf selects double buffer) ---
    auto load_chunk = [&](int c, int buf) {
        const int kg = (bh << 11) + (c << 7);
        if (tid < 128) {
            sK[buf][tid] = g_qh[kg + tid];
            if (tid < 64) {
                int2 mm = *reinterpret_cast<const int2*>(
                    mask + b * SS + (c << 7) + 2 * tid);
                sMaskP[buf][tid] = (mm.x ? 0x0000FFFFu : 0u) |
                                   (mm.y ? 0xFFFF0000u : 0u);
            }
        } else {
            int u  = (tid - 128) >> 1;             // key pair
            int hf = tid & 1;                      // dim half (4 dims)
            const uint32_t* ka = reinterpret_cast<const uint32_t*>(g_qh + kg + 2 * u);
            const uint32_t* kb = ka + 4;
            uint32_t ua0 = ka[hf * 2], ua1 = ka[hf * 2 + 1];
            uint32_t ub0 = kb[hf * 2], ub1 = kb[hf * 2 + 1];
            sVT[buf][hf * 4 + 0][u] = __byte_perm(ua0, ub0, 0x5410);
            sVT[buf][hf * 4 + 1][u] = __byte_perm(ua0, ub0, 0x7632);
            sVT[buf][hf * 4 + 2][u] = __byte_perm(ua1, ub1, 0x5410);
            sVT[buf][hf * 4 + 3][u] = __byte_perm(ua1, ub1, 0x7632);
        }
    };

    load_chunk(0, 0);
    __syncthreads();

    for (int c = 0; c < 16; c++) {
        const int buf = c & 1;
        if (c < 15) load_chunk(c + 1, buf ^ 1);

        const uint32_t* k32 = reinterpret_cast<const uint32_t*>(sK[buf]);

        // --- S = (Q*CSCALE)K^T (k8 MMA); fp16 round; exp2 x2; mask by AND ---
        uint32_t P[16][2];
#pragma unroll
        for (int j = 0; j < 16; j++) {
            int key = 8 * j + r;
            uint32_t b0 = k32[key * 4 + m];            // K dims 2m,2m+1
            float D[4] = {0.f, 0.f, 0.f, 0.f};
            mma16808(D, a0, a1, b0, D);
            uint32_t sA, sB, pA, pB;
            asm("cvt.rn.f16x2.f32 %0, %1, %2;" : "=r"(sA) : "f"(D[1]), "f"(D[0]));
            asm("cvt.rn.f16x2.f32 %0, %1, %2;" : "=r"(sB) : "f"(D[3]), "f"(D[2]));
            asm("ex2.approx.f16x2 %0, %1;" : "=r"(pA) : "r"(sA));
            asm("ex2.approx.f16x2 %0, %1;" : "=r"(pB) : "r"(sB));
            uint32_t w = sMaskP[buf][4 * j + m];       // keys 8j+2m, 8j+2m+1
            pA &= w;
            pB &= w;
            P[j][0] = pA;
            P[j][1] = pB;
            // denominator: exact unpack of the SAME masked P (consistency)
            float2 fa = __half22float2(*reinterpret_cast<half2*>(&pA));
            float2 fb = __half22float2(*reinterpret_cast<half2*>(&pB));
            l_lo += fa.x + fa.y;
            l_hi += fb.x + fb.y;
        }

        // --- O += P * V  (8 k16 steps over 128 keys) ---
#pragma unroll
        for (int t = 0; t < 8; t++) {
            uint32_t b0 = sVT[buf][r][t * 8 + m];
            uint32_t b1 = sVT[buf][r][t * 8 + 4 + m];
            mma16816(O, P[2 * t][0], P[2 * t][1], P[2 * t + 1][0], P[2 * t + 1][1],
                     b0, b1, O);
        }
        __syncthreads();
    }

    // --- Reduce denominators across the 4 threads sharing each row ---
    l_lo += __shfl_xor_sync(0xffffffffu, l_lo, 1);
    l_lo += __shfl_xor_sync(0xffffffffu, l_lo, 2);
    l_hi += __shfl_xor_sync(0xffffffffu, l_hi, 1);
    l_hi += __shfl_xor_sync(0xffffffffu, l_hi, 2);
    float inv_lo = 1.0f / l_lo;
    float inv_hi = 1.0f / l_hi;

    const int h  = bh & 31;
    const int q0 = (qt << 7) + wid * 16 + r;
    uint32_t* op = g_attnh + ((size_t)b * SS + q0) * 128 + h * 4 + m;
    half2 o1 = __floats2half2_rn(O[0] * inv_lo, O[1] * inv_lo);
    half2 o2 = __floats2half2_rn(O[2] * inv_hi, O[3] * inv_hi);
    op[0]       = *reinterpret_cast<uint32_t*>(&o1);
    op[8 * 128] = *reinterpret_cast<uint32_t*>(&o2);
}

// ---------------------------------------------------------------------------
// Output projection via fp16 MMA: Y[4096,256] = A @ W^T + b.
// CTA: 64x64 tile, full K=256 staged once (A fp16 + W cvt to fp16).
// ---------------------------------------------------------------------------
__global__ __launch_bounds__(256, 2) void proj_kernel(
    const float* __restrict__ W,
    const float* __restrict__ bo,
    float*       __restrict__ Y)
{
    extern __shared__ uint32_t sh[];     // As: 64*132 u32, Ws: 64*132 u32
    uint32_t* As = sh;
    uint32_t* Ws = sh + 64 * 132;

    const int tid = threadIdx.x;
    const int im0 = blockIdx.x * 64;
    const int jn0 = blockIdx.y * 64;

    // Stage A (already fp16): 64 rows x 128 u32, uint4 loads
#pragma unroll
    for (int l = 0; l < 8; l++) {
        int idx = l * 256 + tid;
        int row = idx >> 5, c4 = idx & 31;
        uint4 v = *reinterpret_cast<const uint4*>(
            g_attnh + (size_t)(im0 + row) * 128 + c4 * 4);
        *reinterpret_cast<uint4*>(As + row * 132 + c4 * 4) = v;
    }
    // Stage W with fp32->fp16 conversion: 64 rows x 64 float4
#pragma unroll
    for (int l = 0; l < 16; l++) {
        int idx = l * 256 + tid;
        int row = idx >> 6, c4 = idx & 63;
        float4 v = *reinterpret_cast<const float4*>(
            W + (size_t)(jn0 + row) * 256 + c4 * 4);
        half2 h0 = __floats2half2_rn(v.x, v.y);
        half2 h1 = __floats2half2_rn(v.z, v.w);
        uint2 pk = make_uint2(*reinterpret_cast<uint32_t*>(&h0),
                              *reinterpret_cast<uint32_t*>(&h1));
        *reinterpret_cast<uint2*>(Ws + row * 132 + c4 * 2) = pk;
    }
    __syncthreads();

    const int lane = tid & 31, wid = tid >> 5;
    const int r = lane >> 2, m = lane & 3;
    const int mb  = (wid & 3) * 16;      // m-block
    const int nb0 = (wid >> 2) * 32;     // 4 n8-blocks

    float acc[4][4];
#pragma unroll
    for (int nn = 0; nn < 4; nn++)
#pragma unroll
        for (int i = 0; i < 4; i++) acc[nn][i] = 0.f;

#pragma unroll
    for (int kc = 0; kc < 16; kc++) {
        uint32_t a0 = As[(mb + r) * 132 + kc * 8 + m];
        uint32_t a1 = As[(mb + r + 8) * 132 + kc * 8 + m];
        uint32_t a2 = As[(mb + r) * 132 + kc * 8 + 4 + m];
        uint32_t a3 = As[(mb + r + 8) * 132 + kc * 8 + 4 + m];
#pragma unroll
        for (int nn = 0; nn < 4; nn++) {
            uint32_t b0 = Ws[(nb0 + nn * 8 + r) * 132 + kc * 8 + m];
            uint32_t b1 = Ws[(nb0 + nn * 8 + r) * 132 + kc * 8 + 4 + m];
            mma16816(acc[nn], a0, a1, a2, a3, b0, b1, acc[nn]);
        }
    }

    // Epilogue: bias + fp32 stores
#pragma unroll
    for (int nn = 0; nn < 4; nn++) {
        int j = jn0 + nb0 + nn * 8 + 2 * m;
        float2 bv = *reinterpret_cast<const float2*>(bo + j);
        int i0 = im0 + mb + r;
        *reinterpret_cast<float2*>(Y + (size_t)i0 * 256 + j) =
            make_float2(acc[nn][0] + bv.x, acc[nn][1] + bv.y);
        *reinterpret_cast<float2*>(Y + (size_t)(i0 + 8) * 256 + j) =
            make_float2(acc[nn][2] + bv.x, acc[nn][3] + bv.y);
    }
}

// ---------------------------------------------------------------------------
extern "C" void kernel_launch(void* const* d_in, const int* in_sizes, int n_in,
                              void* d_out, int out_size)
{
    const float* x     = (const float*)d_in[0];
    const int*   mask  = (const int*)d_in[1];
    const float* theta = (const float*)d_in[2];
    const float* W     = (const float*)d_in[3];
    const float* bo    = (const float*)d_in[4];
    float*       out   = (float*)d_out;

    prep_kernel<<<SS * HH / 256, 256>>>(x, theta);      // 256 blocks
    attn_kernel<<<64 * 16, 256>>>(mask);

    const int proj_smem = 2 * 64 * 132 * 4;   // 67.6 KB
    cudaFuncSetAttribute(proj_kernel,
                         cudaFuncAttributeMaxDynamicSharedMemorySize, proj_smem);
    dim3 grid(BB * SS / 64, EE / 64);  // (64, 4)
    proj_kernel<<<grid, 256, proj_smem>>>(W, bo, out);
}

// round 11
// speedup vs baseline: 1.1002x; 1.0967x over previous
#include <cuda_runtime.h>
#include <cuda_fp16.h>
#include <math.h>
#include <stdint.h>

#define BB 2
#define SS 2048
#define EE 256
#define HH 32

// log2(e)/sqrt(8): folded into the Q fragment.
#define CSCALE 0.51006972790221780093f

__device__ uint32_t g_attnh[BB * SS * EE / 2];  // attention output, fp16x2 [B,S,E]
__device__ uint4 g_qh[64 * 2048];               // fp16 cos(x+theta): 8 vals (16B) per (bh,s)

// Warp-level fp16 MMA m16n8k16, D/C fp32. Baseline sm_80 PTX.
__device__ __forceinline__ void mma16816(float d[4],
    uint32_t a0, uint32_t a1, uint32_t a2, uint32_t a3,
    uint32_t b0, uint32_t b1, const float c[4])
{
    asm volatile("mma.sync.aligned.m16n8k16.row.col.f32.f16.f16.f32 "
        "{%0,%1,%2,%3}, {%4,%5,%6,%7}, {%8,%9}, {%10,%11,%12,%13};"
        : "=f"(d[0]), "=f"(d[1]), "=f"(d[2]), "=f"(d[3])
        : "r"(a0), "r"(a1), "r"(a2), "r"(a3), "r"(b0), "r"(b1),
          "f"(c[0]), "f"(c[1]), "f"(c[2]), "f"(c[3]));
}
// Warp-level fp16 MMA m16n8k8 with FP16 accumulator: D packed f16x2,
// exactly the P-fragment layout (no cvt needed). Baseline sm_75+ PTX.
__device__ __forceinline__ void mma16808h(uint32_t& d0, uint32_t& d1,
    uint32_t a0, uint32_t a1, uint32_t b0)
{
    asm volatile("mma.sync.aligned.m16n8k8.row.col.f16.f16.f16.f16 "
        "{%0,%1}, {%2,%3}, {%4}, {%5,%6};"
        : "=r"(d0), "=r"(d1)
        : "r"(a0), "r"(a1), "r"(b0), "r"(0u), "r"(0u));
}

// ---------------------------------------------------------------------------
// Prep: q = cos(x + theta) -> fp16 via smem transpose.
// Block = (b, 16 tokens): coalesced float4 loads, 8KB smem tile,
// then 256B-contiguous stores per (bh) segment.
// ---------------------------------------------------------------------------
__global__ __launch_bounds__(256) void prep_kernel(
    const float* __restrict__ x,
    const float* __restrict__ theta)
{
    __shared__ uint2 tile[32][34];       // [h][s_local*2 + hf], padded row 272B

    const int t   = threadIdx.x;
    const int blk = blockIdx.x;          // 0..255
    const int b   = blk >> 7;
    const int s0  = (blk & 127) << 4;    // 16 tokens
    float th[8];
#pragma unroll
    for (int d = 0; d < 8; d++) th[d] = __ldg(theta + d);

    const float* xb = x + ((size_t)b * SS + s0) * EE;
#pragma unroll
    for (int l = 0; l < 4; l++) {
        int idx = t + l * 256;           // float4 index, 0..1023
        int row = idx >> 6;              // token 0..15
        int c4  = idx & 63;              // float4 within row
        float4 v = *reinterpret_cast<const float4*>(xb + (size_t)row * EE + c4 * 4);
        int hf = c4 & 1;
        int db = hf * 4;
        half2 h0 = __floats2half2_rn(__cosf(v.x + th[db + 0]), __cosf(v.y + th[db + 1]));
        half2 h1 = __floats2half2_rn(__cosf(v.z + th[db + 2]), __cosf(v.w + th[db + 3]));
        tile[c4 >> 1][row * 2 + hf] =
            make_uint2(*reinterpret_cast<uint32_t*>(&h0),
                       *reinterpret_cast<uint32_t*>(&h1));
    }
    __syncthreads();
#pragma unroll
    for (int l = 0; l < 4; l++) {
        int idx = t + l * 256;           // uint2 index, 0..1023
        int h  = idx >> 5;
        int in = idx & 31;               // s_local*2 + hf
        uint2 v = tile[h][in];
        uint2* dst = reinterpret_cast<uint2*>(g_qh + (((b << 5) + h) << 11) + s0);
        dst[in] = v;
    }
}

// ---------------------------------------------------------------------------
// Warp-MMA flash attention. S via fp16-acc m16n8k8 (packed D -> ex2 direct);
// mask applied by AND-ing packed fp16 P with per-key-pair mask words (exact).
// ---------------------------------------------------------------------------
__global__ __launch_bounds__(256, 3) void attn_kernel(const int* __restrict__ mask)
{
    __shared__ uint4    sK[2][128];      // K tile, 16B (8 fp16) per key
    __shared__ uint32_t sMaskP[2][64];   // packed mask halves per key pair
    __shared__ uint32_t sVT[2][8][68];   // V^T [dim][key-pair fp16x2], padded

    const int tid  = threadIdx.x;
    const int wid  = tid >> 5;
    const int lane = tid & 31;
    const int r = lane >> 2;             // fragment row group
    const int m = lane & 3;              // fragment k group
    const int bh = blockIdx.x >> 4;
    const int qt = blockIdx.x & 15;
    const int b  = bh >> 5;

    // --- Fixed A fragment: this warp's 16 queries, pre-scaled by CSCALE ---
    const int qbase = (bh << 11) + (qt << 7) + wid * 16;
    const uint32_t* qw = reinterpret_cast<const uint32_t*>(g_qh + qbase);
    uint32_t a0r = qw[r * 4 + m];                // row r,   dims 2m,2m+1
    uint32_t a1r = qw[(r + 8) * 4 + m];          // row r+8
    float2 f0 = __half22float2(*reinterpret_cast<half2*>(&a0r));
    float2 f1 = __half22float2(*reinterpret_cast<half2*>(&a1r));
    half2 s0 = __floats2half2_rn(f0.x * CSCALE, f0.y * CSCALE);
    half2 s1 = __floats2half2_rn(f1.x * CSCALE, f1.y * CSCALE);
    const uint32_t a0 = *reinterpret_cast<uint32_t*>(&s0);
    const uint32_t a1 = *reinterpret_cast<uint32_t*>(&s1);

    float O[4] = {0.f, 0.f, 0.f, 0.f};   // output fragment [16q x 8d]
    float l_lo = 0.f, l_hi = 0.f;        // softmax denominators (rows r, r+8)

    // --- Tile loader (buf selects double buffer) ---
    auto load_chunk = [&](int c, int buf) {
        const int kg = (bh << 11) + (c << 7);
        if (tid < 128) {
            sK[buf][tid] = g_qh[kg + tid];
            if (tid < 64) {
                int2 mm = *reinterpret_cast<const int2*>(
                    mask + b * SS + (c << 7) + 2 * tid);
                sMaskP[buf][tid] = (mm.x ? 0x0000FFFFu : 0u) |
                                   (mm.y ? 0xFFFF0000u : 0u);
            }
        } else {
            int u  = (tid - 128) >> 1;             // key pair
            int hf = tid & 1;                      // dim half (4 dims)
            const uint32_t* ka = reinterpret_cast<const uint32_t*>(g_qh + kg + 2 * u);
            const uint32_t* kb = ka + 4;
            uint32_t ua0 = ka[hf * 2], ua1 = ka[hf * 2 + 1];
            uint32_t ub0 = kb[hf * 2], ub1 = kb[hf * 2 + 1];
            sVT[buf][hf * 4 + 0][u] = __byte_perm(ua0, ub0, 0x5410);
            sVT[buf][hf * 4 + 1][u] = __byte_perm(ua0, ub0, 0x7632);
            sVT[buf][hf * 4 + 2][u] = __byte_perm(ua1, ub1, 0x5410);
            sVT[buf][hf * 4 + 3][u] = __byte_perm(ua1, ub1, 0x7632);
        }
    };

    load_chunk(0, 0);
    __syncthreads();

    for (int c = 0; c < 16; c++) {
        const int buf = c & 1;
        if (c < 15) load_chunk(c + 1, buf ^ 1);

        const uint32_t* k32 = reinterpret_cast<const uint32_t*>(sK[buf]);

        // --- S = (Q*CSCALE)K^T (fp16-acc k8 MMA -> packed); exp2; mask AND ---
        uint32_t P[16][2];
#pragma unroll
        for (int j = 0; j < 16; j++) {
            int key = 8 * j + r;
            uint32_t b0 = k32[key * 4 + m];            // K dims 2m,2m+1
            uint32_t d0, d1, pA, pB;
            mma16808h(d0, d1, a0, a1, b0);             // d0={s[r][2m],s[r][2m+1]}
            asm("ex2.approx.f16x2 %0, %1;" : "=r"(pA) : "r"(d0));
            asm("ex2.approx.f16x2 %0, %1;" : "=r"(pB) : "r"(d1));
            uint32_t w = sMaskP[buf][4 * j + m];       // keys 8j+2m, 8j+2m+1
            pA &= w;
            pB &= w;
            P[j][0] = pA;
            P[j][1] = pB;
            // denominator: exact unpack of the SAME masked P (consistency)
            float2 fa = __half22float2(*reinterpret_cast<half2*>(&pA));
            float2 fb = __half22float2(*reinterpret_cast<half2*>(&pB));
            l_lo += fa.x + fa.y;
            l_hi += fb.x + fb.y;
        }

        // --- O += P * V  (8 k16 steps over 128 keys) ---
#pragma unroll
        for (int t = 0; t < 8; t++) {
            uint32_t b0 = sVT[buf][r][t * 8 + m];
            uint32_t b1 = sVT[buf][r][t * 8 + 4 + m];
            mma16816(O, P[2 * t][0], P[2 * t][1], P[2 * t + 1][0], P[2 * t + 1][1],
                     b0, b1, O);
        }
        __syncthreads();
    }

    // --- Reduce denominators across the 4 threads sharing each row ---
    l_lo += __shfl_xor_sync(0xffffffffu, l_lo, 1);
    l_lo += __shfl_xor_sync(0xffffffffu, l_lo, 2);
    l_hi += __shfl_xor_sync(0xffffffffu, l_hi, 1);
    l_hi += __shfl_xor_sync(0xffffffffu, l_hi, 2);
    float inv_lo = 1.0f / l_lo;
    float inv_hi = 1.0f / l_hi;

    const int h  = bh & 31;
    const int q0 = (qt << 7) + wid * 16 + r;
    uint32_t* op = g_attnh + ((size_t)b * SS + q0) * 128 + h * 4 + m;
    half2 o1 = __floats2half2_rn(O[0] * inv_lo, O[1] * inv_lo);
    half2 o2 = __floats2half2_rn(O[2] * inv_hi, O[3] * inv_hi);
    op[0]       = *reinterpret_cast<uint32_t*>(&o1);
    op[8 * 128] = *reinterpret_cast<uint32_t*>(&o2);
}

// ---------------------------------------------------------------------------
// Output projection via fp16 MMA: Y[4096,256] = A @ W^T + b.
// CTA: 64x64 tile, full K=256 staged once (A fp16 + W cvt to fp16).
// ---------------------------------------------------------------------------
__global__ __launch_bounds__(256, 2) void proj_kernel(
    const float* __restrict__ W,
    const float* __restrict__ bo,
    float*       __restrict__ Y)
{
    extern __shared__ uint32_t sh[];     // As: 64*132 u32, Ws: 64*132 u32
    uint32_t* As = sh;
    uint32_t* Ws = sh + 64 * 132;

    const int tid = threadIdx.x;
    const int im0 = blockIdx.x * 64;
    const int jn0 = blockIdx.y * 64;

    // Stage A (already fp16): 64 rows x 128 u32, uint4 loads
#pragma unroll
    for (int l = 0; l < 8; l++) {
        int idx = l * 256 + tid;
        int row = idx >> 5, c4 = idx & 31;
        uint4 v = *reinterpret_cast<const uint4*>(
            g_attnh + (size_t)(im0 + row) * 128 + c4 * 4);
        *reinterpret_cast<uint4*>(As + row * 132 + c4 * 4) = v;
    }
    // Stage W with fp32->fp16 conversion: 64 rows x 64 float4
#pragma unroll
    for (int l = 0; l < 16; l++) {
        int idx = l * 256 + tid;
        int row = idx >> 6, c4 = idx & 63;
        float4 v = *reinterpret_cast<const float4*>(
            W + (size_t)(jn0 + row) * 256 + c4 * 4);
        half2 h0 = __floats2half2_rn(v.x, v.y);
        half2 h1 = __floats2half2_rn(v.z, v.w);
        uint2 pk = make_uint2(*reinterpret_cast<uint32_t*>(&h0),
                              *reinterpret_cast<uint32_t*>(&h1));
        *reinterpret_cast<uint2*>(Ws + row * 132 + c4 * 2) = pk;
    }
    __syncthreads();

    const int lane = tid & 31, wid = tid >> 5;
    const int r = lane >> 2, m = lane & 3;
    const int mb  = (wid & 3) * 16;      // m-block
    const int nb0 = (wid >> 2) * 32;     // 4 n8-blocks

    float acc[4][4];
#pragma unroll
    for (int nn = 0; nn < 4; nn++)
#pragma unroll
        for (int i = 0; i < 4; i++) acc[nn][i] = 0.f;

#pragma unroll
    for (int kc = 0; kc < 16; kc++) {
        uint32_t a0 = As[(mb + r) * 132 + kc * 8 + m];
        uint32_t a1 = As[(mb + r + 8) * 132 + kc * 8 + m];
        uint32_t a2 = As[(mb + r) * 132 + kc * 8 + 4 + m];
        uint32_t a3 = As[(mb + r + 8) * 132 + kc * 8 + 4 + m];
#pragma unroll
        for (int nn = 0; nn < 4; nn++) {
            uint32_t b0 = Ws[(nb0 + nn * 8 + r) * 132 + kc * 8 + m];
            uint32_t b1 = Ws[(nb0 + nn * 8 + r) * 132 + kc * 8 + 4 + m];
            mma16816(acc[nn], a0, a1, a2, a3, b0, b1, acc[nn]);
        }
    }

    // Epilogue: bias + fp32 stores
#pragma unroll
    for (int nn = 0; nn < 4; nn++) {
        int j = jn0 + nb0 + nn * 8 + 2 * m;
        float2 bv = *reinterpret_cast<const float2*>(bo + j);
        int i0 = im0 + mb + r;
        *reinterpret_cast<float2*>(Y + (size_t)i0 * 256 + j) =
            make_float2(acc[nn][0] + bv.x, acc[nn][1] + bv.y);
        *reinterpret_cast<float2*>(Y + (size_t)(i0 + 8) * 256 + j) =
            make_float2(acc[nn][2] + bv.x, acc[nn][3] + bv.y);
    }
}

// ---------------------------------------------------------------------------
extern "C" void kernel_launch(void* const* d_in, const int* in_sizes, int n_in,
                              void* d_out, int out_size)
{
    const float* x     = (const float*)d_in[0];
    const int*   mask  = (const int*)d_in[1];
    const float* theta = (const float*)d_in[2];
    const float* W     = (const float*)d_in[3];
    const float* bo    = (const float*)d_in[4];
    float*       out   = (float*)d_out;

    prep_kernel<<<256, 256>>>(x, theta);
    attn_kernel<<<64 * 16, 256>>>(mask);

    const int proj_smem = 2 * 64 * 132 * 4;   // 67.6 KB
    cudaFuncSetAttribute(proj_kernel,
                         cudaFuncAttributeMaxDynamicSharedMemorySize, proj_smem);
    dim3 grid(BB * SS / 64, EE / 64);  // (64, 4)
    proj_kernel<<<grid, 256, proj_smem>>>(W, bo, out);
}

// round 12
// speedup vs baseline: 1.1063x; 1.0055x over previous
#include <cuda_runtime.h>
#include <cuda_fp16.h>
#include <math.h>
#include <stdint.h>

#define BB 2
#define SS 2048
#define EE 256
#define HH 32

// log2(e)/sqrt(8): folded into the Q fragment.
#define CSCALE 0.51006972790221780093f

__device__ uint32_t g_attnh[BB * SS * EE / 2];  // attention output, fp16x2 [B,S,E]
__device__ uint4 g_qh[64 * 2048];               // fp16 cos(x+theta): 8 vals (16B) per (bh,s)

// Warp-level fp16 MMA m16n8k16, D/C fp32. Baseline sm_80 PTX.
__device__ __forceinline__ void mma16816(float d[4],
    uint32_t a0, uint32_t a1, uint32_t a2, uint32_t a3,
    uint32_t b0, uint32_t b1, const float c[4])
{
    asm volatile("mma.sync.aligned.m16n8k16.row.col.f32.f16.f16.f32 "
        "{%0,%1,%2,%3}, {%4,%5,%6,%7}, {%8,%9}, {%10,%11,%12,%13};"
        : "=f"(d[0]), "=f"(d[1]), "=f"(d[2]), "=f"(d[3])
        : "r"(a0), "r"(a1), "r"(a2), "r"(a3), "r"(b0), "r"(b1),
          "f"(c[0]), "f"(c[1]), "f"(c[2]), "f"(c[3]));
}
// Warp-level fp16 MMA m16n8k8 with FP16 accumulator: D packed f16x2,
// exactly the P-fragment layout (no cvt needed). Baseline sm_75+ PTX.
__device__ __forceinline__ void mma16808h(uint32_t& d0, uint32_t& d1,
    uint32_t a0, uint32_t a1, uint32_t b0)
{
    asm volatile("mma.sync.aligned.m16n8k8.row.col.f16.f16.f16.f16 "
        "{%0,%1}, {%2,%3}, {%4}, {%5,%6};"
        : "=r"(d0), "=r"(d1)
        : "r"(a0), "r"(a1), "r"(b0), "r"(0u), "r"(0u));
}

// ---------------------------------------------------------------------------
// Prep: q = cos(x + theta) -> fp16 via smem transpose.
// Block = (b, 8 tokens): coalesced float4 loads, 4KB smem tile,
// then 64B-contiguous stores per (bh) segment. 512 blocks (2x R11 occupancy).
// ---------------------------------------------------------------------------
__global__ __launch_bounds__(256) void prep_kernel(
    const float* __restrict__ x,
    const float* __restrict__ theta)
{
    __shared__ uint2 tile[32][18];       // [h][s_local*2 + hf], padded

    const int t   = threadIdx.x;
    const int blk = blockIdx.x;          // 0..511
    const int b   = blk >> 8;
    const int s0  = (blk & 255) << 3;    // 8 tokens
    float th[8];
#pragma unroll
    for (int d = 0; d < 8; d++) th[d] = __ldg(theta + d);

    const float* xb = x + ((size_t)b * SS + s0) * EE;
#pragma unroll
    for (int l = 0; l < 2; l++) {
        int idx = t + l * 256;           // float4 index, 0..511
        int row = idx >> 6;              // token 0..7
        int c4  = idx & 63;              // float4 within row
        float4 v = *reinterpret_cast<const float4*>(xb + (size_t)row * EE + c4 * 4);
        int hf = c4 & 1;
        int db = hf * 4;
        half2 h0 = __floats2half2_rn(__cosf(v.x + th[db + 0]), __cosf(v.y + th[db + 1]));
        half2 h1 = __floats2half2_rn(__cosf(v.z + th[db + 2]), __cosf(v.w + th[db + 3]));
        tile[c4 >> 1][row * 2 + hf] =
            make_uint2(*reinterpret_cast<uint32_t*>(&h0),
                       *reinterpret_cast<uint32_t*>(&h1));
    }
    __syncthreads();
#pragma unroll
    for (int l = 0; l < 2; l++) {
        int idx = t + l * 256;           // uint2 index, 0..511
        int h  = idx >> 4;
        int in = idx & 15;               // s_local*2 + hf
        uint2 v = tile[h][in];
        uint2* dst = reinterpret_cast<uint2*>(g_qh + (((b << 5) + h) << 11) + s0);
        dst[in] = v;
    }
}

// ---------------------------------------------------------------------------
// Warp-MMA flash attention. S via fp16-acc m16n8k8; S and PV interleaved
// (P lives 4 regs, occ 4). Mask applied by AND on packed fp16 P (exact).
// ---------------------------------------------------------------------------
__global__ __launch_bounds__(256, 4) void attn_kernel(const int* __restrict__ mask)
{
    __shared__ uint4    sK[2][128];      // K tile, 16B (8 fp16) per key
    __shared__ uint32_t sMaskP[2][64];   // packed mask halves per key pair
    __shared__ uint32_t sVT[2][8][68];   // V^T [dim][key-pair fp16x2], padded

    const int tid  = threadIdx.x;
    const int wid  = tid >> 5;
    const int lane = tid & 31;
    const int r = lane >> 2;             // fragment row group
    const int m = lane & 3;              // fragment k group
    const int bh = blockIdx.x >> 4;
    const int qt = blockIdx.x & 15;
    const int b  = bh >> 5;

    // --- Fixed A fragment: this warp's 16 queries, pre-scaled by CSCALE ---
    const int qbase = (bh << 11) + (qt << 7) + wid * 16;
    const uint32_t* qw = reinterpret_cast<const uint32_t*>(g_qh + qbase);
    uint32_t a0r = qw[r * 4 + m];                // row r,   dims 2m,2m+1
    uint32_t a1r = qw[(r + 8) * 4 + m];          // row r+8
    float2 f0 = __half22float2(*reinterpret_cast<half2*>(&a0r));
    float2 f1 = __half22float2(*reinterpret_cast<half2*>(&a1r));
    half2 s0 = __floats2half2_rn(f0.x * CSCALE, f0.y * CSCALE);
    half2 s1 = __floats2half2_rn(f1.x * CSCALE, f1.y * CSCALE);
    const uint32_t a0 = *reinterpret_cast<uint32_t*>(&s0);
    const uint32_t a1 = *reinterpret_cast<uint32_t*>(&s1);

    float O[4] = {0.f, 0.f, 0.f, 0.f};   // output fragment [16q x 8d]
    float l_lo = 0.f, l_hi = 0.f;        // softmax denominators (rows r, r+8)

    // --- Tile loader (buf selects double buffer) ---
    auto load_chunk = [&](int c, int buf) {
        const int kg = (bh << 11) + (c << 7);
        if (tid < 128) {
            sK[buf][tid] = g_qh[kg + tid];
            if (tid < 64) {
                int2 mm = *reinterpret_cast<const int2*>(
                    mask + b * SS + (c << 7) + 2 * tid);
                sMaskP[buf][tid] = (mm.x ? 0x0000FFFFu : 0u) |
                                   (mm.y ? 0xFFFF0000u : 0u);
            }
        } else {
            int u  = (tid - 128) >> 1;             // key pair
            int hf = tid & 1;                      // dim half (4 dims)
            const uint32_t* ka = reinterpret_cast<const uint32_t*>(g_qh + kg + 2 * u);
            const uint32_t* kb = ka + 4;
            uint32_t ua0 = ka[hf * 2], ua1 = ka[hf * 2 + 1];
            uint32_t ub0 = kb[hf * 2], ub1 = kb[hf * 2 + 1];
            sVT[buf][hf * 4 + 0][u] = __byte_perm(ua0, ub0, 0x5410);
            sVT[buf][hf * 4 + 1][u] = __byte_perm(ua0, ub0, 0x7632);
            sVT[buf][hf * 4 + 2][u] = __byte_perm(ua1, ub1, 0x5410);
            sVT[buf][hf * 4 + 3][u] = __byte_perm(ua1, ub1, 0x7632);
        }
    };

    load_chunk(0, 0);
    __syncthreads();

    for (int c = 0; c < 16; c++) {
        const int buf = c & 1;
        if (c < 15) load_chunk(c + 1, buf ^ 1);

        const uint32_t* k32 = reinterpret_cast<const uint32_t*>(sK[buf]);

        // --- Interleaved: S for key-pairs 2t,2t+1 then PV MMA t ---
#pragma unroll
        for (int t = 0; t < 8; t++) {
            uint32_t P00, P01, P10, P11;
            {
                int key = 16 * t + r;                  // j = 2t
                uint32_t kb0 = k32[key * 4 + m];
                uint32_t d0, d1;
                mma16808h(d0, d1, a0, a1, kb0);
                asm("ex2.approx.f16x2 %0, %1;" : "=r"(P00) : "r"(d0));
                asm("ex2.approx.f16x2 %0, %1;" : "=r"(P01) : "r"(d1));
                uint32_t w = sMaskP[buf][8 * t + m];
                P00 &= w;
                P01 &= w;
                float2 fa = __half22float2(*reinterpret_cast<half2*>(&P00));
                float2 fb = __half22float2(*reinterpret_cast<half2*>(&P01));
                l_lo += fa.x + fa.y;
                l_hi += fb.x + fb.y;
            }
            {
                int key = 16 * t + 8 + r;              // j = 2t+1
                uint32_t kb0 = k32[key * 4 + m];
                uint32_t d0, d1;
                mma16808h(d0, d1, a0, a1, kb0);
                asm("ex2.approx.f16x2 %0, %1;" : "=r"(P10) : "r"(d0));
                asm("ex2.approx.f16x2 %0, %1;" : "=r"(P11) : "r"(d1));
                uint32_t w = sMaskP[buf][8 * t + 4 + m];
                P10 &= w;
                P11 &= w;
                float2 fa = __half22float2(*reinterpret_cast<half2*>(&P10));
                float2 fb = __half22float2(*reinterpret_cast<half2*>(&P11));
                l_lo += fa.x + fa.y;
                l_hi += fb.x + fb.y;
            }
            uint32_t vb0 = sVT[buf][r][t * 8 + m];
            uint32_t vb1 = sVT[buf][r][t * 8 + 4 + m];
            mma16816(O, P00, P01, P10, P11, vb0, vb1, O);
        }
        __syncthreads();
    }

    // --- Reduce denominators across the 4 threads sharing each row ---
    l_lo += __shfl_xor_sync(0xffffffffu, l_lo, 1);
    l_lo += __shfl_xor_sync(0xffffffffu, l_lo, 2);
    l_hi += __shfl_xor_sync(0xffffffffu, l_hi, 1);
    l_hi += __shfl_xor_sync(0xffffffffu, l_hi, 2);
    float inv_lo = 1.0f / l_lo;
    float inv_hi = 1.0f / l_hi;

    const int h  = bh & 31;
    const int q0 = (qt << 7) + wid * 16 + r;
    uint32_t* op = g_attnh + ((size_t)b * SS + q0) * 128 + h * 4 + m;
    half2 o1 = __floats2half2_rn(O[0] * inv_lo, O[1] * inv_lo);
    half2 o2 = __floats2half2_rn(O[2] * inv_hi, O[3] * inv_hi);
    op[0]       = *reinterpret_cast<uint32_t*>(&o1);
    op[8 * 128] = *reinterpret_cast<uint32_t*>(&o2);
}

// ---------------------------------------------------------------------------
// Output projection via fp16 MMA: Y[4096,256] = A @ W^T + b.
// CTA: 64x64 tile, full K=256 staged once (A fp16 + W cvt to fp16).
// ---------------------------------------------------------------------------
__global__ __launch_bounds__(256, 2) void proj_kernel(
    const float* __restrict__ W,
    const float* __restrict__ bo,
    float*       __restrict__ Y)
{
    extern __shared__ uint32_t sh[];     // As: 64*132 u32, Ws: 64*132 u32
    uint32_t* As = sh;
    uint32_t* Ws = sh + 64 * 132;

    const int tid = threadIdx.x;
    const int im0 = blockIdx.x * 64;
    const int jn0 = blockIdx.y * 64;

    // Stage A (already fp16): 64 rows x 128 u32, uint4 loads
#pragma unroll
    for (int l = 0; l < 8; l++) {
        int idx = l * 256 + tid;
        int row = idx >> 5, c4 = idx & 31;
        uint4 v = *reinterpret_cast<const uint4*>(
            g_attnh + (size_t)(im0 + row) * 128 + c4 * 4);
        *reinterpret_cast<uint4*>(As + row * 132 + c4 * 4) = v;
    }
    // Stage W with fp32->fp16 conversion: 64 rows x 64 float4
#pragma unroll
    for (int l = 0; l < 16; l++) {
        int idx = l * 256 + tid;
        int row = idx >> 6, c4 = idx & 63;
        float4 v = *reinterpret_cast<const float4*>(
            W + (size_t)(jn0 + row) * 256 + c4 * 4);
        half2 h0 = __floats2half2_rn(v.x, v.y);
        half2 h1 = __floats2half2_rn(v.z, v.w);
        uint2 pk = make_uint2(*reinterpret_cast<uint32_t*>(&h0),
                              *reinterpret_cast<uint32_t*>(&h1));
        *reinterpret_cast<uint2*>(Ws + row * 132 + c4 * 2) = pk;
    }
    __syncthreads();

    const int lane = tid & 31, wid = tid >> 5;
    const int r = lane >> 2, m = lane & 3;
    const int mb  = (wid & 3) * 16;      // m-block
    const int nb0 = (wid >> 2) * 32;     // 4 n8-blocks

    float acc[4][4];
#pragma unroll
    for (int nn = 0; nn < 4; nn++)
#pragma unroll
        for (int i = 0; i < 4; i++) acc[nn][i] = 0.f;

#pragma unroll
    for (int kc = 0; kc < 16; kc++) {
        uint32_t a0 = As[(mb + r) * 132 + kc * 8 + m];
        uint32_t a1 = As[(mb + r + 8) * 132 + kc * 8 + m];
        uint32_t a2 = As[(mb + r) * 132 + kc * 8 + 4 + m];
        uint32_t a3 = As[(mb + r + 8) * 132 + kc * 8 + 4 + m];
#pragma unroll
        for (int nn = 0; nn < 4; nn++) {
            uint32_t b0 = Ws[(nb0 + nn * 8 + r) * 132 + kc * 8 + m];
            uint32_t b1 = Ws[(nb0 + nn * 8 + r) * 132 + kc * 8 + 4 + m];
            mma16816(acc[nn], a0, a1, a2, a3, b0, b1, acc[nn]);
        }
    }

    // Epilogue: bias + fp32 stores
#pragma unroll
    for (int nn = 0; nn < 4; nn++) {
        int j = jn0 + nb0 + nn * 8 + 2 * m;
        float2 bv = *reinterpret_cast<const float2*>(bo + j);
        int i0 = im0 + mb + r;
        *reinterpret_cast<float2*>(Y + (size_t)i0 * 256 + j) =
            make_float2(acc[nn][0] + bv.x, acc[nn][1] + bv.y);
        *reinterpret_cast<float2*>(Y + (size_t)(i0 + 8) * 256 + j) =
            make_float2(acc[nn][2] + bv.x, acc[nn][3] + bv.y);
    }
}

// ---------------------------------------------------------------------------
extern "C" void kernel_launch(void* const* d_in, const int* in_sizes, int n_in,
                              void* d_out, int out_size)
{
    const float* x     = (const float*)d_in[0];
    const int*   mask  = (const int*)d_in[1];
    const float* theta = (const float*)d_in[2];
    const float* W     = (const float*)d_in[3];
    const float* bo    = (const float*)d_in[4];
    float*       out   = (float*)d_out;

    prep_kernel<<<512, 256>>>(x, theta);
    attn_kernel<<<64 * 16, 256>>>(mask);

    const int proj_smem = 2 * 64 * 132 * 4;   // 67.6 KB
    cudaFuncSetAttribute(proj_kernel,
                         cudaFuncAttributeMaxDynamicSharedMemorySize, proj_smem);
    dim3 grid(BB * SS / 64, EE / 64);  // (64, 4)
    proj_kernel<<<grid, 256, proj_smem>>>(W, bo, out);
}